// round 1
// baseline (speedup 1.0000x reference)
#include <cuda_runtime.h>
#include <cstdint>
#include <cstddef>

#define NB 8
#define NH 128
#define NW 128
#define CI 256
#define CO 256
#define NL 512
#define NPIX (NB*NH*NW)

#define C_STD  0.0625f
#define C_CONV 0.02946278254943948f
#define C_D1   0.08838834764831845f
#define C_D2   0.04419417382415922f

// ---------------- scratch (static device allocations; no runtime alloc) ----
__device__ float g_s[NB*CI];
__device__ float g_d[NB*CO];
__device__ float g_xs[(size_t)NPIX*CI];      // modulated, tf32-rounded input
__device__ float g_wc[9*CI*CO];              // scaled tf32 conv weights
__device__ float g_w1[CO*4*CO];              // scaled tf32 D1 weights
__device__ float g_w2[4*CO*CO];              // scaled tf32 D2 weights
__device__ float g_y[(size_t)NPIX*CO];       // conv output (post-lrelu, tf32)
__device__ float g_h[(size_t)NPIX*4*CO];     // D1 output (post-lrelu, tf32)

// ---------------- helpers --------------------------------------------------
__device__ __forceinline__ float to_tf32(float x){
    float r; asm("cvt.rna.tf32.f32 %0, %1;" : "=f"(r) : "f"(x)); return r;
}
__device__ __forceinline__ float lrelu(float x){ return x > 0.f ? x : 0.2f*x; }

__device__ __forceinline__ void mma8(float c[4], const uint32_t a[4], const uint32_t b[2]){
    asm volatile("mma.sync.aligned.m16n8k8.row.col.f32.tf32.tf32.f32 "
        "{%0,%1,%2,%3}, {%4,%5,%6,%7}, {%8,%9}, {%0,%1,%2,%3};\n"
        : "+f"(c[0]), "+f"(c[1]), "+f"(c[2]), "+f"(c[3])
        : "r"(a[0]), "r"(a[1]), "r"(a[2]), "r"(a[3]), "r"(b[0]), "r"(b[1]));
}
__device__ __forceinline__ void cp16(uint32_t d, const void* s, int nbytes){
    asm volatile("cp.async.ca.shared.global [%0], [%1], 16, %2;\n"
                 :: "r"(d), "l"(s), "r"(nbytes));
}
__device__ __forceinline__ void cp_commit(){ asm volatile("cp.async.commit_group;\n"); }
template<int N> __device__ __forceinline__ void cp_wait(){
    asm volatile("cp.async.wait_group %0;\n" :: "n"(N));
}

// ---------------- tile layout ----------------------------------------------
struct Tiles {
    float A[128][36];    // [M][K] padded (36: conflict-free quad access)
    float Bm[32][136];   // [K][N] padded (136 -> 8k+dn distinct banks)
};

__device__ __forceinline__ void compute_tile(const Tiles& t, float acc[2][8][4],
                                             int wm, int wn, int qr, int qc){
#pragma unroll
    for (int kk = 0; kk < 4; kk++){
        uint32_t a[2][4];
#pragma unroll
        for (int mt = 0; mt < 2; mt++){
            int row = wm*32 + mt*16 + qr;
            a[mt][0] = __float_as_uint(t.A[row  ][kk*8+qc  ]);
            a[mt][1] = __float_as_uint(t.A[row+8][kk*8+qc  ]);
            a[mt][2] = __float_as_uint(t.A[row  ][kk*8+qc+4]);
            a[mt][3] = __float_as_uint(t.A[row+8][kk*8+qc+4]);
        }
        uint32_t b[8][2];
#pragma unroll
        for (int nt = 0; nt < 8; nt++){
            int n = wn*64 + nt*8 + qr;
            b[nt][0] = __float_as_uint(t.Bm[kk*8+qc  ][n]);
            b[nt][1] = __float_as_uint(t.Bm[kk*8+qc+4][n]);
        }
#pragma unroll
        for (int mt = 0; mt < 2; mt++)
#pragma unroll
            for (int nt = 0; nt < 8; nt++)
                mma8(acc[mt][nt], a[mt], b[nt]);
    }
}

// ---------------- prep kernels ---------------------------------------------
__global__ void s_kernel(const float* __restrict__ latent,
                         const float* __restrict__ stdW,
                         const float* __restrict__ stdb){
    int b = blockIdx.x, i = threadIdx.x;
    float acc = 0.f;
    for (int l = 0; l < NL; l++) acc += latent[b*NL+l] * stdW[l*CI+i];
    g_s[b*CI+i] = acc * C_STD + stdb[i];
}

__global__ void d_kernel(const float* __restrict__ cw){
    int b = blockIdx.x, o = threadIdx.x;
    float acc = 0.f;
    for (int i = 0; i < CI; i++){
        float w2 = 0.f;
#pragma unroll
        for (int k = 0; k < 9; k++){
            float wv = cw[(size_t)(k*CI + i)*CO + o];
            w2 += wv*wv;
        }
        float sv = g_s[b*CI+i];
        acc += w2 * sv * sv;
    }
    g_d[b*CO+o] = rsqrtf(acc * (C_CONV*C_CONV) + 1e-8f);
}

__global__ void mod_kernel(const float* __restrict__ data){
    size_t idx = ((size_t)blockIdx.x * blockDim.x + threadIdx.x) * 4;
    float4 x = *(const float4*)(data + idx);
    int c = (int)(idx & (CI-1));
    int b = (int)(idx >> 22);         // / (128*128*256)
    float4 s = *(const float4*)(g_s + b*CI + c);
    float4 r;
    r.x = to_tf32(x.x*s.x); r.y = to_tf32(x.y*s.y);
    r.z = to_tf32(x.z*s.z); r.w = to_tf32(x.w*s.w);
    *(float4*)(g_xs + idx) = r;
}

__global__ void wscale_kernel(const float* __restrict__ src, float* __restrict__ dst,
                              float sc, int n4){
    int idx = blockIdx.x * blockDim.x + threadIdx.x;
    if (idx < n4){
        float4 v = *(const float4*)(src + (size_t)idx*4);
        float4 r;
        r.x = to_tf32(v.x*sc); r.y = to_tf32(v.y*sc);
        r.z = to_tf32(v.z*sc); r.w = to_tf32(v.w*sc);
        *(float4*)(dst + (size_t)idx*4) = r;
    }
}

// ---------------- conv (implicit GEMM) -------------------------------------
__device__ __forceinline__ void issue_conv(Tiles* t, int b, int h, int n0,
                                           int kc, int tid){
    int ktap = kc >> 3, ci0 = (kc & 7) * 32;
    int dh = ktap/3 - 1, dw = ktap%3 - 1;
    int hp = h + dh;
    bool hv = (unsigned)hp < NH;
#pragma unroll
    for (int j = 0; j < 4; j++){
        int lin = tid + j*256;
        int wrow = lin >> 3, c4 = (lin & 7) * 4;
        int wp = wrow + dw;
        bool v = hv && ((unsigned)wp < NW);
        const float* src = v ? (g_xs + ((size_t)((b*NH+hp)*NW + wp))*CI + ci0 + c4)
                             : (const float*)g_xs;
        cp16((uint32_t)__cvta_generic_to_shared(&t->A[wrow][c4]), src, v ? 16 : 0);
        int kk = lin >> 5, n4 = (lin & 31) * 4;
        cp16((uint32_t)__cvta_generic_to_shared(&t->Bm[kk][n4]),
             g_wc + (size_t)((ktap*CI + ci0 + kk)*CO) + n0 + n4, 16);
    }
    cp_commit();
}

__global__ void __launch_bounds__(256,2) conv_kernel(
    const float* __restrict__ bias, const float* __restrict__ noise,
    const float* __restrict__ ncoef)
{
    extern __shared__ Tiles tiles[];
    int tid = threadIdx.x;
    int bh = blockIdx.y; int b = bh >> 7, h = bh & 127;
    int n0 = blockIdx.x * 128;
    int wid = tid >> 5, lane = tid & 31;
    int wm = wid >> 1, wn = wid & 1, qr = lane >> 2, qc = lane & 3;

    float acc[2][8][4];
#pragma unroll
    for (int i = 0; i < 2; i++)
#pragma unroll
        for (int j = 0; j < 8; j++)
#pragma unroll
            for (int k = 0; k < 4; k++) acc[i][j][k] = 0.f;

    const int NK = 72;
    issue_conv(&tiles[0], b, h, n0, 0, tid);
#pragma unroll 1
    for (int kc = 0; kc < NK; kc++){
        if (kc + 1 < NK){ issue_conv(&tiles[(kc+1)&1], b, h, n0, kc+1, tid); cp_wait<1>(); }
        else            { cp_wait<0>(); }
        __syncthreads();
        compute_tile(tiles[kc&1], acc, wm, wn, qr, qc);
        __syncthreads();
    }

    size_t prow = (size_t)(b*NH + h) * NW;
#pragma unroll
    for (int mt = 0; mt < 2; mt++){
#pragma unroll
        for (int nt = 0; nt < 8; nt++){
            int col = n0 + wn*64 + nt*8 + 2*qc;
            float d0 = g_d[b*CO+col], d1 = g_d[b*CO+col+1];
            float b0 = bias[col], b1 = bias[col+1];
            float nc0 = ncoef[col], nc1 = ncoef[col+1];
#pragma unroll
            for (int r2 = 0; r2 < 2; r2++){
                int w = wm*32 + mt*16 + qr + r2*8;
                size_t p = prow + w;
                float2 nz = *(const float2*)(noise + p*CO + col);
                float v0 = acc[mt][nt][r2*2+0]*d0 + b0 + nz.x*nc0;
                float v1 = acc[mt][nt][r2*2+1]*d1 + b1 + nz.y*nc1;
                v0 = to_tf32(lrelu(v0));
                v1 = to_tf32(lrelu(v1));
                *(float2*)(g_y + p*CO + col) = make_float2(v0, v1);
            }
        }
    }
}

// ---------------- generic GEMM (A,B pre-rounded tf32) ----------------------
template<int K, int N>
__device__ __forceinline__ void issue_gemm(Tiles* t, const float* A, const float* Bw,
                                           size_t m0, int n0, int kc, int tid){
#pragma unroll
    for (int j = 0; j < 4; j++){
        int lin = tid + j*256;
        int row = lin >> 3, c4 = (lin & 7) * 4;
        cp16((uint32_t)__cvta_generic_to_shared(&t->A[row][c4]),
             A + (m0 + row)*(size_t)K + (size_t)kc*32 + c4, 16);
        int kk = lin >> 5, n4 = (lin & 31) * 4;
        cp16((uint32_t)__cvta_generic_to_shared(&t->Bm[kk][n4]),
             Bw + (size_t)(kc*32 + kk)*N + n0 + n4, 16);
    }
    cp_commit();
}

template<int K, int N, bool ROUND>
__global__ void __launch_bounds__(256,2) gemm_kernel(
    const float* __restrict__ A, const float* __restrict__ Bw,
    const float* __restrict__ bias, float* __restrict__ out)
{
    extern __shared__ Tiles tiles[];
    int tid = threadIdx.x;
    size_t m0 = (size_t)blockIdx.y * 128;
    int n0 = blockIdx.x * 128;
    int wid = tid >> 5, lane = tid & 31;
    int wm = wid >> 1, wn = wid & 1, qr = lane >> 2, qc = lane & 3;

    float acc[2][8][4];
#pragma unroll
    for (int i = 0; i < 2; i++)
#pragma unroll
        for (int j = 0; j < 8; j++)
#pragma unroll
            for (int k = 0; k < 4; k++) acc[i][j][k] = 0.f;

    const int NK = K/32;
    issue_gemm<K,N>(&tiles[0], A, Bw, m0, n0, 0, tid);
#pragma unroll 1
    for (int kc = 0; kc < NK; kc++){
        if (kc + 1 < NK){ issue_gemm<K,N>(&tiles[(kc+1)&1], A, Bw, m0, n0, kc+1, tid); cp_wait<1>(); }
        else            { cp_wait<0>(); }
        __syncthreads();
        compute_tile(tiles[kc&1], acc, wm, wn, qr, qc);
        __syncthreads();
    }

#pragma unroll
    for (int mt = 0; mt < 2; mt++){
#pragma unroll
        for (int nt = 0; nt < 8; nt++){
            int col = n0 + wn*64 + nt*8 + 2*qc;
            float b0 = bias[col], b1 = bias[col+1];
#pragma unroll
            for (int r2 = 0; r2 < 2; r2++){
                size_t m = m0 + wm*32 + mt*16 + qr + r2*8;
                float v0 = lrelu(acc[mt][nt][r2*2+0] + b0);
                float v1 = lrelu(acc[mt][nt][r2*2+1] + b1);
                if (ROUND){ v0 = to_tf32(v0); v1 = to_tf32(v1); }
                *(float2*)(out + m*(size_t)N + col) = make_float2(v0, v1);
            }
        }
    }
}

// ---------------- launch ----------------------------------------------------
extern "C" void kernel_launch(void* const* d_in, const int* in_sizes, int n_in,
                              void* d_out, int out_size){
    const float* data   = (const float*)d_in[0];
    const float* latent = (const float*)d_in[1];
    const float* noise  = (const float*)d_in[2];
    const float* stdW   = (const float*)d_in[3];
    const float* stdb   = (const float*)d_in[4];
    const float* convw  = (const float*)d_in[5];
    const float* bias   = (const float*)d_in[6];
    const float* ncoef  = (const float*)d_in[7];
    const float* d1w    = (const float*)d_in[8];
    const float* d1b    = (const float*)d_in[9];
    const float* d2w    = (const float*)d_in[10];
    const float* d2b    = (const float*)d_in[11];
    float* out = (float*)d_out;

    void *p_wc, *p_w1, *p_w2, *p_y, *p_h;
    cudaGetSymbolAddress(&p_wc, g_wc);
    cudaGetSymbolAddress(&p_w1, g_w1);
    cudaGetSymbolAddress(&p_w2, g_w2);
    cudaGetSymbolAddress(&p_y,  g_y);
    cudaGetSymbolAddress(&p_h,  g_h);

    int smem = (int)sizeof(Tiles) * 2;  // 71680 B, double-buffered
    cudaFuncSetAttribute(conv_kernel, cudaFuncAttributeMaxDynamicSharedMemorySize, smem);
    cudaFuncSetAttribute(gemm_kernel<256,1024,true>,  cudaFuncAttributeMaxDynamicSharedMemorySize, smem);
    cudaFuncSetAttribute(gemm_kernel<1024,256,false>, cudaFuncAttributeMaxDynamicSharedMemorySize, smem);

    s_kernel<<<NB, CI>>>(latent, stdW, stdb);
    d_kernel<<<NB, CO>>>(convw);
    mod_kernel<<<32768, 256>>>(data);
    wscale_kernel<<<(9*CI*CO/4 + 255)/256, 256>>>(convw, (float*)p_wc, C_CONV, 9*CI*CO/4);
    wscale_kernel<<<(CO*4*CO/4 + 255)/256, 256>>>(d1w,  (float*)p_w1, C_D1,  CO*4*CO/4);
    wscale_kernel<<<(4*CO*CO/4 + 255)/256, 256>>>(d2w,  (float*)p_w2, C_D2,  4*CO*CO/4);

    conv_kernel<<<dim3(2,1024), 256, smem>>>(bias, noise, ncoef);
    gemm_kernel<256,1024,true ><<<dim3(8,1024), 256, smem>>>((const float*)p_y, (const float*)p_w1, d1b, (float*)p_h);
    gemm_kernel<1024,256,false><<<dim3(2,1024), 256, smem>>>((const float*)p_h, (const float*)p_w2, d2b, out);
}